// round 6
// baseline (speedup 1.0000x reference)
#include <cuda_runtime.h>
#include <math.h>
#include <stdint.h>

// Problem constants
#define HNUM 256
#define WNUM 256
#define MC   128
#define NSQ  32
#define RR   (NSQ * NSQ)     // 1024
#define TT   512
#define BIN_LEN 0.02f
#define EPS_NORM 1e-12f

// Output layout (all float32, concatenated flattened tuple):
//   origins_out  (MC,RR,3) | directions (MC,RR,3) | t (MC,RR,TT) | xys (MC,RR,2)
#define OFF_ORI 0
#define OFF_DIR (MC * RR * 3)                          // 393216
#define OFF_T   (2 * MC * RR * 3)                      // 786432
#define OFF_XYS (2 * MC * RR * 3 + MC * RR * TT)       // 67895296

#define NTHREADS 1024

__device__ __forceinline__ float norm3(float a, float b, float c) {
    return sqrtf(__fadd_rn(__fadd_rn(__fmul_rn(a, a), __fmul_rn(b, b)), __fmul_rn(c, c)));
}

// ---------------------------------------------------------------------------
// Single fused kernel. One block per m (grid=128, 1024 threads, 32 warps).
//  Phase 0: warp 0 computes per-m scalars into shared (incl. idx dtype sniff)
//  Phase A: thread t computes row t's (dx^2, dy^2, dx*l) into shared float4
//  Phase B: warp w owns rows [w*32, w*32+32). Rows processed in tiles of 4
//           CONSECUTIVE rows (dense 8KB store region per tile):
//            - hoist the 4 rows' (dx2,dy2,dxl) from shared (4x LDS.128)
//            - per j (4 bins): tau/tau2/diff computed ONCE (12 regs),
//              reused across the 4 rows -> row-invariant chain amortized 4x
//            - per row: 4x(num,den,fast-div,nan-setp) + 1 STG.128 (stcs)
//  Per-m NaN flag -> in-block rewrite with t_conf (rare path).
// num/den/dx/dy arithmetic is op-for-op identical to the reference ordering;
// only the final division is __fdividef (validated: rel_err ~6e-8).
// ---------------------------------------------------------------------------
__global__ void __launch_bounds__(NTHREADS, 1)
fused_kernel(const float* __restrict__ laser_pos,
             const float* __restrict__ camera_pos,
             const float* __restrict__ laser_origin,
             const float* __restrict__ camera_origin,
             const float* __restrict__ dirs,
             const int*   __restrict__ idx_raw,
             float* __restrict__ out) {
    __shared__ float4 s_row[RR];              // (dx2, dy2, dxl, 0) per row
    __shared__ float s_orig[3], s_lvec[3];
    __shared__ float s_l, s_eff, s_d1d4, s_y, s_x;
    __shared__ int   s_flag;

    const int m   = blockIdx.x;
    const int tid = threadIdx.x;

    // ---- Phase 0: per-m scalar setup (warp 0) ----
    if (tid < 32) {
        // dtype sniff: int64 little-endian => high words of first 32 elems are 0
        int hz = (idx_raw[2 * tid + 1] == 0);
        unsigned ball = __ballot_sync(0xffffffffu, hz);
        int is64 = (__popc(ball) >= 2);

        if (tid == 0) {
            long long idx = is64 ? ((const long long*)idx_raw)[m]
                                 : (long long)idx_raw[m];
            int y = (int)(idx / WNUM);
            int x = (int)(idx % WNUM);
            if (m == 0) { y = HNUM / 2; x = WNUM / 2; }

            int base = (y * WNUM + x) * 3;
            float lpx = laser_pos[base + 0], lpy = laser_pos[base + 1], lpz = laser_pos[base + 2];
            float cpx = camera_pos[base + 0], cpy = camera_pos[base + 1], cpz = camera_pos[base + 2];

            float d1 = norm3(__fsub_rn(lpx, laser_origin[0]),
                             __fsub_rn(lpy, laser_origin[1]),
                             __fsub_rn(lpz, laser_origin[2]));
            float d4 = norm3(__fsub_rn(cpx, camera_origin[0]),
                             __fsub_rn(cpy, camera_origin[1]),
                             __fsub_rn(cpz, camera_origin[2]));
            float d1d4 = __fadd_rn(d1, d4);

            float vx = __fsub_rn(lpx, cpx);
            float vy = __fsub_rn(lpy, cpy);
            float vz = __fsub_rn(lpz, cpz);
            float l  = norm3(vx, vy, vz);
            float inv = __fdiv_rn(1.0f, fmaxf(l, EPS_NORM));

            float off_f = ceilf(__fdiv_rn(__fsub_rn(l, d1d4), BIN_LEN));
            int offset = (int)off_f;
            int eff = offset % TT;
            if (eff < 0) eff += TT;

            s_orig[0] = cpx; s_orig[1] = cpy; s_orig[2] = cpz;
            s_lvec[0] = __fmul_rn(vx, inv);
            s_lvec[1] = __fmul_rn(vy, inv);
            s_lvec[2] = __fmul_rn(vz, inv);
            s_l = l; s_d1d4 = d1d4; s_eff = (float)eff;
            s_y = (float)y; s_x = (float)x;
            s_flag = 0;
        }
    }
    __syncthreads();

    const float lvx = s_lvec[0], lvy = s_lvec[1], lvz = s_lvec[2];
    const float ox  = s_orig[0], oy  = s_orig[1], oz  = s_orig[2];
    const float l   = s_l;
    const float eff = s_eff;
    const float yv  = s_y, xv = s_x;
    const float l2  = __fmul_rn(l, l);

    // ---- Phase A: per-row (dx2, dy2, dxl) into shared ----
    {
        const int r = tid;
        const float d0 = __ldg(&dirs[r * 3 + 0]);
        const float d1 = __ldg(&dirs[r * 3 + 1]);
        const float d2 = __ldg(&dirs[r * 3 + 2]);
        float dx  = __fadd_rn(__fadd_rn(__fmul_rn(d0, lvx), __fmul_rn(d1, lvy)),
                              __fmul_rn(d2, lvz));
        float dx2 = __fmul_rn(dx, dx);
        float dy  = sqrtf(__fsub_rn(1.0f, dx2));   // NaN if dx2 > 1 (propagates)
        float dy2 = __fmul_rn(dy, dy);
        float dxl = __fmul_rn(dx, l);
        s_row[r] = make_float4(dx2, dy2, dxl, 0.0f);
    }

    // ---- small outputs for this m (coalesced) ----
    {
        float* po = out + OFF_ORI + (size_t)m * (RR * 3);
        float* pd = out + OFF_DIR + (size_t)m * (RR * 3);
        #pragma unroll
        for (int i = tid; i < RR * 3; i += NTHREADS) {
            int c = i % 3;
            po[i] = (c == 0) ? ox : (c == 1) ? oy : oz;
            pd[i] = __ldg(&dirs[i]);
        }
        float* pxy = out + OFF_XYS + (size_t)m * (RR * 2);
        #pragma unroll
        for (int i = tid; i < RR * 2; i += NTHREADS) {
            pxy[i] = (i & 1) ? xv : yv;
        }
    }
    __syncthreads();

    // ---- Phase B: t tensor. Warp owns 32 consecutive rows; 4-row tiles. ----
    const int warp = tid >> 5;
    const int lane = tid & 31;
    bool anynan = false;
    float4* tbase = (float4*)(out + OFF_T) + (size_t)m * RR * (TT / 4);
    const int row0 = warp * 32;

    #pragma unroll 1
    for (int tile = 0; tile < 8; tile++) {
        const int rt = row0 + tile * 4;
        // Hoist the 4 rows' coefficients (independent LDS.128s).
        float4 c0 = s_row[rt + 0];
        float4 c1 = s_row[rt + 1];
        float4 c2 = s_row[rt + 2];
        float4 c3 = s_row[rt + 3];

        #pragma unroll
        for (int j = 0; j < 4; j++) {
            const int i4 = j * 32 + lane;
            // Row-invariant per-bin values (exact reference rounding),
            // computed once per tile (amortized over 4 rows).
            float tau[4], tau2[4], diff[4];
            #pragma unroll
            for (int k = 0; k < 4; k++) {
                float tf = (float)(i4 * 4 + k);
                tau[k]  = __fmul_rn(BIN_LEN, fmaxf(tf, eff));
                tau2[k] = __fmul_rn(tau[k], tau[k]);
                diff[k] = __fsub_rn(tau2[k], l2);
            }
            #pragma unroll
            for (int i = 0; i < 4; i++) {
                float4 c = (i == 0) ? c0 : (i == 1) ? c1 : (i == 2) ? c2 : c3;
                const float dx2 = c.x, dy2 = c.y, dxl = c.z;
                float4 v4;
                #pragma unroll
                for (int k = 0; k < 4; k++) {
                    float num = __fmul_rn(__fadd_rn(dxl, tau[k]), diff[k]);
                    float den = __fmul_rn(2.0f,
                                  __fadd_rn(__fmul_rn(dx2, diff[k]),
                                            __fmul_rn(dy2, tau2[k])));
                    float v   = __fdividef(num, den);
                    anynan |= (v != v);
                    ((float*)&v4)[k] = v;
                }
                __stcs(&tbase[(size_t)(rt + i) * (TT / 4) + i4], v4);
            }
        }
    }

    // ---- NaN flag reduce + in-block fixup (rare path) ----
    unsigned ball = __ballot_sync(0xffffffffu, anynan);
    if (ball != 0u && lane == 0) atomicOr(&s_flag, 1);
    __syncthreads();

    if (s_flag) {
        const float d1d4 = s_d1d4;
        float4 c4[4];
        #pragma unroll
        for (int j = 0; j < 4; j++) {
            const int i4 = j * 32 + lane;
            #pragma unroll
            for (int k = 0; k < 4; k++) {
                float tau0 = __fmul_rn((float)(i4 * 4 + k), BIN_LEN);
                float d = __fsub_rn(tau0, d1d4);
                if (d <= 0.0f) d = 1e-6f;
                ((float*)&c4[j])[k] = __fmul_rn(d, 0.5f);
            }
        }
        #pragma unroll 1
        for (int rr = 0; rr < 32; rr++) {
            const int r = row0 + rr;
            #pragma unroll
            for (int j = 0; j < 4; j++) {
                tbase[(size_t)r * (TT / 4) + j * 32 + lane] = c4[j];
            }
        }
    }
}

// ---------------------------------------------------------------------------
extern "C" void kernel_launch(void* const* d_in, const int* in_sizes, int n_in,
                              void* d_out, int out_size) {
    const float* laser_pos     = (const float*)d_in[0];
    const float* camera_pos    = (const float*)d_in[1];
    const float* laser_origin  = (const float*)d_in[2];
    const float* camera_origin = (const float*)d_in[3];
    const float* directions    = (const float*)d_in[4];
    const int*   idx_raw       = (const int*)d_in[5];
    float* out = (float*)d_out;

    fused_kernel<<<MC, NTHREADS>>>(laser_pos, camera_pos, laser_origin,
                                   camera_origin, directions, idx_raw, out);
}

// round 8
// speedup vs baseline: 1.2459x; 1.2459x over previous
#include <cuda_runtime.h>
#include <math.h>
#include <stdint.h>

// Problem constants
#define HNUM 256
#define WNUM 256
#define MC   128
#define NSQ  32
#define RR   (NSQ * NSQ)     // 1024
#define TT   512
#define BIN_LEN 0.02f
#define EPS_NORM 1e-12f

// Output layout (all float32, concatenated flattened tuple):
//   origins_out  (MC,RR,3) | directions (MC,RR,3) | t (MC,RR,TT) | xys (MC,RR,2)
#define OFF_ORI 0
#define OFF_DIR (MC * RR * 3)                          // 393216
#define OFF_T   (2 * MC * RR * 3)                      // 786432
#define OFF_XYS (2 * MC * RR * 3 + MC * RR * TT)       // 67895296

#define NTHREADS 1024

__device__ __forceinline__ float norm3(float a, float b, float c) {
    return sqrtf(__fadd_rn(__fadd_rn(__fmul_rn(a, a), __fmul_rn(b, b)), __fmul_rn(c, c)));
}

// ---------------------------------------------------------------------------
// Single fused kernel. One block per m (grid=128, 1024 threads, 32 warps).
// Structure = Round-3 (best: 44.5us) + per-bin shared table:
//  Phase 0: warp 0 computes per-m scalars into shared (incl. idx dtype sniff)
//  Phase A: thread t computes row t's (dx^2, dy^2, dx*l) into s_row (float4)
//  Phase A2: threads 0..511 fill SoA tables s_tau/s_tau2/s_diff[512]
//            (tau, tau^2, tau^2-l^2 per t-bin; row-invariant, exact rounding)
//  Phase B: warp-per-row, row-major (identical store order to R3):
//            per j: 3x conflict-free LDS.128 (4 consecutive bins from each
//            SoA table) + 4x(num,den,fast-div,nan-setp) + 1 STG.128 (stcs)
//  Per-m NaN flag -> in-block rewrite with t_conf (rare path).
// num/den/dx/dy rounding is op-for-op identical to the reference ordering;
// only the final division is __fdividef (validated: rel_err ~6e-8).
// Live-register footprint kept small deliberately (R5/R6 regressions were
// consistent with spilling at the 64-reg cap).
// ---------------------------------------------------------------------------
__global__ void __launch_bounds__(NTHREADS, 1)
fused_kernel(const float* __restrict__ laser_pos,
             const float* __restrict__ camera_pos,
             const float* __restrict__ laser_origin,
             const float* __restrict__ camera_origin,
             const float* __restrict__ dirs,
             const int*   __restrict__ idx_raw,
             float* __restrict__ out) {
    __shared__ float4 s_row[RR];              // (dx2, dy2, dxl, 0) per row
    __shared__ float  s_tau[TT];              // BIN_LEN * max(t, eff)
    __shared__ float  s_tau2[TT];             // tau^2
    __shared__ float  s_diff[TT];             // tau^2 - l^2
    __shared__ float  s_orig[3], s_lvec[3];
    __shared__ float  s_l, s_eff, s_d1d4, s_y, s_x;
    __shared__ int    s_flag;

    const int m   = blockIdx.x;
    const int tid = threadIdx.x;

    // ---- Phase 0: per-m scalar setup (warp 0) ----
    if (tid < 32) {
        // dtype sniff: int64 little-endian => high words of first 32 elems are 0
        int hz = (idx_raw[2 * tid + 1] == 0);
        unsigned ball = __ballot_sync(0xffffffffu, hz);
        int is64 = (__popc(ball) >= 2);

        if (tid == 0) {
            long long idx = is64 ? ((const long long*)idx_raw)[m]
                                 : (long long)idx_raw[m];
            int y = (int)(idx / WNUM);
            int x = (int)(idx % WNUM);
            if (m == 0) { y = HNUM / 2; x = WNUM / 2; }

            int base = (y * WNUM + x) * 3;
            float lpx = laser_pos[base + 0], lpy = laser_pos[base + 1], lpz = laser_pos[base + 2];
            float cpx = camera_pos[base + 0], cpy = camera_pos[base + 1], cpz = camera_pos[base + 2];

            float d1 = norm3(__fsub_rn(lpx, laser_origin[0]),
                             __fsub_rn(lpy, laser_origin[1]),
                             __fsub_rn(lpz, laser_origin[2]));
            float d4 = norm3(__fsub_rn(cpx, camera_origin[0]),
                             __fsub_rn(cpy, camera_origin[1]),
                             __fsub_rn(cpz, camera_origin[2]));
            float d1d4 = __fadd_rn(d1, d4);

            float vx = __fsub_rn(lpx, cpx);
            float vy = __fsub_rn(lpy, cpy);
            float vz = __fsub_rn(lpz, cpz);
            float l  = norm3(vx, vy, vz);
            float inv = __fdiv_rn(1.0f, fmaxf(l, EPS_NORM));

            float off_f = ceilf(__fdiv_rn(__fsub_rn(l, d1d4), BIN_LEN));
            int offset = (int)off_f;
            int eff = offset % TT;
            if (eff < 0) eff += TT;

            s_orig[0] = cpx; s_orig[1] = cpy; s_orig[2] = cpz;
            s_lvec[0] = __fmul_rn(vx, inv);
            s_lvec[1] = __fmul_rn(vy, inv);
            s_lvec[2] = __fmul_rn(vz, inv);
            s_l = l; s_d1d4 = d1d4; s_eff = (float)eff;
            s_y = (float)y; s_x = (float)x;
            s_flag = 0;
        }
    }
    __syncthreads();

    const float lvx = s_lvec[0], lvy = s_lvec[1], lvz = s_lvec[2];
    const float ox  = s_orig[0], oy  = s_orig[1], oz  = s_orig[2];
    const float l   = s_l;
    const float eff = s_eff;
    const float yv  = s_y, xv = s_x;
    const float l2  = __fmul_rn(l, l);

    // ---- Phase A: per-row (dx2, dy2, dxl) into shared ----
    {
        const int r = tid;
        const float d0 = __ldg(&dirs[r * 3 + 0]);
        const float d1 = __ldg(&dirs[r * 3 + 1]);
        const float d2 = __ldg(&dirs[r * 3 + 2]);
        float dx  = __fadd_rn(__fadd_rn(__fmul_rn(d0, lvx), __fmul_rn(d1, lvy)),
                              __fmul_rn(d2, lvz));
        float dx2 = __fmul_rn(dx, dx);
        float dy  = sqrtf(__fsub_rn(1.0f, dx2));   // NaN if dx2 > 1 (propagates)
        float dy2 = __fmul_rn(dy, dy);
        float dxl = __fmul_rn(dx, l);
        s_row[r] = make_float4(dx2, dy2, dxl, 0.0f);
    }

    // ---- Phase A2: per-bin tables (exact reference rounding) ----
    if (tid < TT) {
        float tf   = (float)tid;
        float tau  = __fmul_rn(BIN_LEN, fmaxf(tf, eff));
        float tau2 = __fmul_rn(tau, tau);
        s_tau[tid]  = tau;
        s_tau2[tid] = tau2;
        s_diff[tid] = __fsub_rn(tau2, l2);
    }

    // ---- small outputs for this m (coalesced) ----
    {
        float* po = out + OFF_ORI + (size_t)m * (RR * 3);
        float* pd = out + OFF_DIR + (size_t)m * (RR * 3);
        #pragma unroll
        for (int i = tid; i < RR * 3; i += NTHREADS) {
            int c = i % 3;
            po[i] = (c == 0) ? ox : (c == 1) ? oy : oz;
            pd[i] = __ldg(&dirs[i]);
        }
        float* pxy = out + OFF_XYS + (size_t)m * (RR * 2);
        #pragma unroll
        for (int i = tid; i < RR * 2; i += NTHREADS) {
            pxy[i] = (i & 1) ? xv : yv;
        }
    }
    __syncthreads();

    // ---- Phase B: t tensor, warp-per-row (R3 order) ----
    const int warp = tid >> 5;
    const int lane = tid & 31;
    bool anynan = false;
    float4* tbase = (float4*)(out + OFF_T) + (size_t)m * RR * (TT / 4);
    const float4* t_tau  = (const float4*)s_tau;
    const float4* t_tau2 = (const float4*)s_tau2;
    const float4* t_diff = (const float4*)s_diff;

    #pragma unroll 1
    for (int rw = 0; rw < 32; rw++) {
        const int r = rw * 32 + warp;
        float4 c = s_row[r];                   // broadcast LDS.128
        const float dx2 = c.x, dy2 = c.y, dxl = c.z;

        #pragma unroll
        for (int j = 0; j < 4; j++) {
            const int i4 = j * 32 + lane;
            // 4 consecutive bins: conflict-free LDS.128 per SoA table.
            float4 tau4  = t_tau[i4];
            float4 tau24 = t_tau2[i4];
            float4 diff4 = t_diff[i4];
            float4 v4;
            #pragma unroll
            for (int k = 0; k < 4; k++) {
                float tau  = ((const float*)&tau4)[k];
                float tau2 = ((const float*)&tau24)[k];
                float diff = ((const float*)&diff4)[k];
                float num  = __fmul_rn(__fadd_rn(dxl, tau), diff);
                float den  = __fmul_rn(2.0f,
                               __fadd_rn(__fmul_rn(dx2, diff),
                                         __fmul_rn(dy2, tau2)));
                float v    = __fdividef(num, den);
                anynan |= (v != v);
                ((float*)&v4)[k] = v;
            }
            __stcs(&tbase[(size_t)r * (TT / 4) + i4], v4);
        }
    }

    // ---- NaN flag reduce + in-block fixup (rare path) ----
    unsigned ball = __ballot_sync(0xffffffffu, anynan);
    if (ball != 0u && lane == 0) atomicOr(&s_flag, 1);
    __syncthreads();

    if (s_flag) {
        const float d1d4 = s_d1d4;
        float4 c4[4];
        #pragma unroll
        for (int j = 0; j < 4; j++) {
            const int i4 = j * 32 + lane;
            #pragma unroll
            for (int k = 0; k < 4; k++) {
                float tau0 = __fmul_rn((float)(i4 * 4 + k), BIN_LEN);
                float d = __fsub_rn(tau0, d1d4);
                if (d <= 0.0f) d = 1e-6f;
                ((float*)&c4[j])[k] = __fmul_rn(d, 0.5f);
            }
        }
        #pragma unroll 1
        for (int rw = 0; rw < 32; rw++) {
            const int r = rw * 32 + warp;
            #pragma unroll
            for (int j = 0; j < 4; j++) {
                tbase[(size_t)r * (TT / 4) + j * 32 + lane] = c4[j];
            }
        }
    }
}

// ---------------------------------------------------------------------------
extern "C" void kernel_launch(void* const* d_in, const int* in_sizes, int n_in,
                              void* d_out, int out_size) {
    const float* laser_pos     = (const float*)d_in[0];
    const float* camera_pos    = (const float*)d_in[1];
    const float* laser_origin  = (const float*)d_in[2];
    const float* camera_origin = (const float*)d_in[3];
    const float* directions    = (const float*)d_in[4];
    const int*   idx_raw       = (const int*)d_in[5];
    float* out = (float*)d_out;

    fused_kernel<<<MC, NTHREADS>>>(laser_pos, camera_pos, laser_origin,
                                   camera_origin, directions, idx_raw, out);
}